// round 16
// baseline (speedup 1.0000x reference)
#include <cuda_runtime.h>
#include <cuda_fp16.h>
#include <cstdint>
#include <math.h>

#define NAB 4096
#define NA  2048
#define NN  48
#define FF  128
#define NPAIR (NAB*NN)       // 196608
#define NTILES (NPAIR/128)   // 1536
#define RCUT 5.0f

// packed pair-granule strides (bytes/row): ST/4 ≡ 4 (mod 32) -> conflict-free
#define ST1 144   // K=64:  4 ksteps * 32B + 16 pad
#define ST2 272   // K=128: 8 ksteps * 32B + 16 pad

// dynamic smem byte offsets (filter kernel)
#define SM_G   0                      // 128*144 = 18432
#define SM_H   18432                  // 128*272 = 34816
#define SM_B1  53248                  // 128*144 = 18432
#define SM_B2  71680                  // 128*272 = 34816
#define SM_TOT 106496                 // 104 KB -> 2 CTAs/SM

// Scratch (__device__ globals; no allocations allowed)
__device__ float g_Q[NAB*FF];
__device__ float g_K[NAB*FF];
__device__ float g_V[NAB*FF];

// ---------------------------------------------------------------------------
__device__ __forceinline__ float sspf(float z){
    float az = fabsf(z);
    float e = __expf(-az);
    return fmaxf(z, 0.f) + __logf(1.f + e) - 0.69314718055994531f;
}

__device__ __forceinline__ uint32_t pack2h(float a, float b){
    return ((uint32_t)__half_as_ushort(__float2half(b)) << 16) |
           (uint32_t)__half_as_ushort(__float2half(a));
}

// packed pair addr: 8B granule = {pair(k,k+1), pair(k+8,k+9)} per row
__device__ __forceinline__ uint32_t pkP(int row, int k, int st){
    return (uint32_t)(row*st + ((k >> 4) << 5) + (((k & 7) >> 1) << 3) + ((k & 8) >> 1));
}

__device__ __forceinline__ void mma_f16(float* c, uint32_t a0, uint32_t a1, uint32_t a2, uint32_t a3,
                                        uint32_t b0, uint32_t b1){
    asm volatile(
        "mma.sync.aligned.m16n8k16.row.col.f32.f16.f16.f32 "
        "{%0,%1,%2,%3}, {%4,%5,%6,%7}, {%8,%9}, {%0,%1,%2,%3};"
        : "+f"(c[0]), "+f"(c[1]), "+f"(c[2]), "+f"(c[3])
        : "r"(a0), "r"(a1), "r"(a2), "r"(a3), "r"(b0), "r"(b1));
}

// fp16 single-pass GEMM: warp tile 32x64 (2 m-frags x 8 n-frags)
template<int KSTEPS, int ST>
__device__ __forceinline__ void gemm1p(
    const char* __restrict__ A, const char* __restrict__ Bm,
    int m0, int n0, int lane, float acc[2][8][4])
{
    const int rq = lane >> 2, q = lane & 3;
    #pragma unroll
    for (int ks = 0; ks < KSTEPS; ks++){
        const char* Ab = A + ks*32 + q*8;
        const char* Bb = Bm + ks*32 + q*8;
        uint2 a0[2], a1[2], bb[8];
        #pragma unroll
        for (int mf = 0; mf < 2; mf++){
            a0[mf] = *(const uint2*)(Ab + (m0 + mf*16 + rq)*ST);
            a1[mf] = *(const uint2*)(Ab + (m0 + mf*16 + 8 + rq)*ST);
        }
        #pragma unroll
        for (int nf = 0; nf < 8; nf++)
            bb[nf] = *(const uint2*)(Bb + (n0 + nf*8 + rq)*ST);
        #pragma unroll
        for (int mf = 0; mf < 2; mf++)
            #pragma unroll
            for (int nf = 0; nf < 8; nf++)
                mma_f16(acc[mf][nf], a0[mf].x, a1[mf].x, a0[mf].y, a1[mf].y, bb[nf].x, bb[nf].y);
    }
}

// ---------------------------------------------------------------------------
// Persistent fused filter network (pure fp16 HMMA), 256 threads / 8 warps,
// 2 CTAs per SM for cross-CTA phase overlap
// ---------------------------------------------------------------------------
__global__ void __launch_bounds__(256,2) filter_kernel(
    const float* __restrict__ f_ij, const float* __restrict__ r_ij,
    const float* __restrict__ Wf1, const float* __restrict__ bf1,
    const float* __restrict__ Wf2, const float* __restrict__ bf2,
    float* __restrict__ outW)
{
    extern __shared__ __align__(128) char dynsm[];
    __shared__ float s_cw[128], s_bf1[128], s_bf2[128];

    char* G  = dynsm + SM_G;
    char* H  = dynsm + SM_H;
    char* B1 = dynsm + SM_B1;
    char* B2 = dynsm + SM_B2;

    const int tid  = threadIdx.x;
    const int lane = tid & 31, wid = tid >> 5;
    const int m0 = (wid & 3) * 32;
    const int n0 = (wid >> 2) * 64;
    const int rq = lane >> 2, q = lane & 3;

    // ---- weight prep (once per persistent block): transpose + pack fp16 ----
    for (int i = tid; i < 128*32; i += 256){
        int n = i >> 5, p = i & 31, k = p*2;
        float v0 = (k   < 50) ? Wf1[k*FF + n]     : 0.f;
        float v1 = (k+1 < 50) ? Wf1[(k+1)*FF + n] : 0.f;
        *(uint32_t*)(B1 + pkP(n, k, ST1)) = pack2h(v0, v1);
    }
    for (int i = tid; i < 128*64; i += 256){
        int n = i >> 6, p = i & 63, k = p*2;
        *(uint32_t*)(B2 + pkP(n, k, ST2)) = pack2h(Wf2[k*FF + n], Wf2[(k+1)*FF + n]);
    }
    if (tid < 128){ s_bf1[tid] = bf1[tid]; s_bf2[tid] = bf2[tid]; }

    for (int t = blockIdx.x; t < NTILES; t += gridDim.x){
        const int tb = t * 128;

        // ---- load tile: G = 2*f_ij - 1 packed fp16; cutoff weights ----
        for (int i = tid; i < 128*32; i += 256){
            int row = i >> 5, gp = i & 31, gk = gp*2;
            float2 v = (gp < 25) ? *(const float2*)(f_ij + (size_t)(tb+row)*50 + gk)
                                 : make_float2(0.5f, 0.5f);
            *(uint32_t*)(G + pkP(row, gk, ST1)) = pack2h(2.f*v.x - 1.f, 2.f*v.y - 1.f);
        }
        if (tid < 128){
            float r = r_ij[tb + tid];
            s_cw[tid] = (r < RCUT) ? 0.5f*(__cosf(0.62831853071795865f*r) + 1.f) : 0.f;
        }
        __syncthreads();   // S1: G + s_cw(t) visible

        // cutoff weights for this warp's rows -> regs
        float rcw0 = s_cw[m0 + rq],      rcw1 = s_cw[m0 + rq + 8];
        float rcw2 = s_cw[m0 + 16 + rq], rcw3 = s_cw[m0 + 16 + rq + 8];

        // ---- GEMM1: D1 = G @ Wf1 ----
        float acc[2][8][4];
        #pragma unroll
        for (int mf=0;mf<2;mf++)
            #pragma unroll
            for (int nf=0;nf<8;nf++)
                #pragma unroll
                for (int u=0;u<4;u++) acc[mf][nf][u] = 0.f;
        gemm1p<4, ST1>(G, B1, m0, n0, lane, acc);

        // ---- epilogue 1: H = ssp(D1 + bf1) -> fp16 packed into H ----
        #pragma unroll
        for (int mf = 0; mf < 2; mf++){
            const int r = m0 + mf*16 + rq;
            #pragma unroll
            for (int nfp = 0; nfp < 8; nfp += 2){
                int ccA = n0 + nfp*8 + 2*q;
                int ccB = ccA + 8;
                float b0 = s_bf1[ccA], b1 = s_bf1[ccA+1];
                float b2 = s_bf1[ccB], b3 = s_bf1[ccB+1];
                uint32_t ad = pkP(r, ccA, ST2);
                uint2 w0, w1;
                w0.x = pack2h(sspf(acc[mf][nfp][0]+b0),   sspf(acc[mf][nfp][1]+b1));
                w0.y = pack2h(sspf(acc[mf][nfp+1][0]+b2), sspf(acc[mf][nfp+1][1]+b3));
                *(uint2*)(H + ad) = w0;
                w1.x = pack2h(sspf(acc[mf][nfp][2]+b0),   sspf(acc[mf][nfp][3]+b1));
                w1.y = pack2h(sspf(acc[mf][nfp+1][2]+b2), sspf(acc[mf][nfp+1][3]+b3));
                *(uint2*)(H + ad + 8*ST2) = w1;
            }
        }
        __syncthreads();   // S2: all GEMM1 reads of G done, H ready

        // ---- GEMM2: D2 = H @ Wf2 ----
        #pragma unroll
        for (int mf=0;mf<2;mf++)
            #pragma unroll
            for (int nf=0;nf<8;nf++)
                #pragma unroll
                for (int u=0;u<4;u++) acc[mf][nf][u] = 0.f;
        gemm1p<8, ST2>(H, B2, m0, n0, lane, acc);

        // ---- epilogue 2: W = (D2 + bf2) * cutoff, direct global store ----
        #pragma unroll
        for (int mf = 0; mf < 2; mf++){
            int rr = m0 + mf*16 + rq;
            float cw0 = mf ? rcw2 : rcw0;
            float cw1 = mf ? rcw3 : rcw1;
            #pragma unroll
            for (int nf = 0; nf < 8; nf++){
                int cc = n0 + nf*8 + 2*q;
                float b0 = s_bf2[cc], b1 = s_bf2[cc+1];
                float2 o0, o1;
                o0.x = (acc[mf][nf][0] + b0) * cw0;
                o0.y = (acc[mf][nf][1] + b1) * cw0;
                o1.x = (acc[mf][nf][2] + b0) * cw1;
                o1.y = (acc[mf][nf][3] + b1) * cw1;
                *(float2*)&outW[((size_t)(tb + rr))*FF + cc]     = o0;
                *(float2*)&outW[((size_t)(tb + rr + 8))*FF + cc] = o1;
            }
        }
        // next-iteration G writes are safe: all warps passed S2 (GEMM1 done),
        // GEMM2/epi2 touch only H + regs; s_cw reads were cached post-S1.
    }
}

// ---------------------------------------------------------------------------
// QKV: x @ {Wq,Wk,Wv}, 64-row x 64-col blocks (gridDim.y = 6)
// ---------------------------------------------------------------------------
__global__ void __launch_bounds__(256) qkv_kernel(
    const float* __restrict__ x,
    const float* __restrict__ Wq, const float* __restrict__ Wk, const float* __restrict__ Wv)
{
    extern __shared__ char dynsm[];
    float* sW = (float*)dynsm;          // [128][64] = 32 KB
    float* sX = sW + FF*64;             // [64][128] = 32 KB
    const int mat  = blockIdx.y >> 1;
    const int half = blockIdx.y & 1;
    const float* Wsrc = (mat == 0) ? Wq : (mat == 1 ? Wk : Wv);
    float* outp = (mat == 0) ? g_Q : (mat == 1 ? g_K : g_V);
    const int tid = threadIdx.x;
    const int row0 = blockIdx.x * 64;

    for (int i = tid; i < FF*32; i += 256){
        int k = i >> 5, c2 = (i & 31)*2;
        *(float2*)&sW[k*64 + c2] = *(const float2*)&Wsrc[k*FF + half*64 + c2];
    }
    for (int i = tid*4; i < 64*FF; i += 1024)
        *(float4*)&sX[i] = *(const float4*)&x[(size_t)row0*FF + i];
    __syncthreads();

    const int lane = tid & 31, wd = tid >> 5;
    const int c0 = lane * 2;
    float acc[8][2];
    #pragma unroll
    for (int m=0;m<8;m++){ acc[m][0]=0.f; acc[m][1]=0.f; }

    for (int k = 0; k < FF; k += 4){
        float2 bf[4];
        #pragma unroll
        for (int kk=0;kk<4;kk++) bf[kk] = *(float2*)&sW[(k+kk)*64 + c0];
        #pragma unroll
        for (int m=0;m<8;m++){
            float4 av = *(float4*)&sX[(wd*8+m)*FF + k];
            acc[m][0] = fmaf(av.x, bf[0].x, acc[m][0]); acc[m][1] = fmaf(av.x, bf[0].y, acc[m][1]);
            acc[m][0] = fmaf(av.y, bf[1].x, acc[m][0]); acc[m][1] = fmaf(av.y, bf[1].y, acc[m][1]);
            acc[m][0] = fmaf(av.z, bf[2].x, acc[m][0]); acc[m][1] = fmaf(av.z, bf[2].y, acc[m][1]);
            acc[m][0] = fmaf(av.w, bf[3].x, acc[m][0]); acc[m][1] = fmaf(av.w, bf[3].y, acc[m][1]);
        }
    }
    #pragma unroll
    for (int m=0;m<8;m++){
        int r = row0 + wd*8 + m;
        *(float2*)&outp[(size_t)r*FF + half*64 + c0] = make_float2(acc[m][0], acc[m][1]);
    }
}

// ---------------------------------------------------------------------------
// Attention aggregation + fused output projection (untouched)
// ---------------------------------------------------------------------------
__global__ void __launch_bounds__(128) attn_out_kernel(
    const int* __restrict__ neighbors, const int* __restrict__ pmask,
    const float* __restrict__ W,
    const float* __restrict__ Wo, const float* __restrict__ bo,
    float* __restrict__ outM)
{
    __shared__ float s_q[128];
    __shared__ float s_sc[64];
    __shared__ float s_at[64];
    __shared__ float s_m[128];
    __shared__ int s_nb[48];
    __shared__ int s_mk[48];
    const int atom = blockIdx.x;
    const int tid = threadIdx.x, lane = tid & 31, wd = tid >> 5;

    s_q[tid] = g_Q[(size_t)atom*FF + tid];
    if (tid < NN){
        s_nb[tid] = neighbors[atom*NN + tid] + (atom >> 11)*NA;
        s_mk[tid] = pmask[atom*NN + tid];
    }
    __syncthreads();

    for (int j = wd; j < 49; j += 4){
        int row = j ? s_nb[j-1] : atom;
        float4 kv = *(const float4*)&g_K[(size_t)row*FF + lane*4];
        float4 qv = *(const float4*)&s_q[lane*4];
        float d = kv.x*qv.x + kv.y*qv.y + kv.z*qv.z + kv.w*qv.w;
        #pragma unroll
        for (int o=16;o;o>>=1) d += __shfl_xor_sync(0xffffffffu, d, o);
        if (lane == 0){
            float s = d * 0.08838834764831845f;  // 1/sqrt(128)
            if (j > 0 && s_mk[j-1] == 0) s = -1e9f;
            s_sc[j] = s;
        }
    }
    __syncthreads();

    if (wd == 0){
        float v0 = (lane      < 49) ? s_sc[lane]      : -3.4e38f;
        float v1 = (lane + 32 < 49) ? s_sc[lane + 32] : -3.4e38f;
        float mx = fmaxf(v0, v1);
        #pragma unroll
        for (int o=16;o;o>>=1) mx = fmaxf(mx, __shfl_xor_sync(0xffffffffu, mx, o));
        float e0 = (lane      < 49) ? __expf(v0 - mx) : 0.f;
        float e1 = (lane + 32 < 49) ? __expf(v1 - mx) : 0.f;
        float s = e0 + e1;
        #pragma unroll
        for (int o=16;o;o>>=1) s += __shfl_xor_sync(0xffffffffu, s, o);
        float inv = 1.f / s;
        if (lane      < 49) s_at[lane]      = e0 * inv;
        if (lane + 32 < 49) s_at[lane + 32] = e1 * inv;
    }
    __syncthreads();

    float acc = s_at[0] * g_V[(size_t)atom*FF + tid];
    const float* wrow = W + (size_t)atom*NN*FF + tid;
    #pragma unroll 4
    for (int j = 0; j < NN; j++)
        acc += s_at[j+1] * g_V[(size_t)s_nb[j]*FF + tid] * wrow[(size_t)j*FF];
    s_m[tid] = acc;
    __syncthreads();

    // fused: out = ssp(m @ Wo + bo); lanes read Wo rows coalesced (L1/L2-resident)
    float o0 = 0.f, o1 = 0.f;
    #pragma unroll 8
    for (int k = 0; k < FF; k += 2){
        o0 = fmaf(s_m[k],   Wo[(size_t)k*FF + tid],     o0);
        o1 = fmaf(s_m[k+1], Wo[(size_t)(k+1)*FF + tid], o1);
    }
    outM[(size_t)atom*FF + tid] = sspf(o0 + o1 + bo[tid]);
}

// ---------------------------------------------------------------------------
extern "C" void kernel_launch(void* const* d_in, const int* in_sizes, int n_in,
                              void* d_out, int out_size)
{
    // order: e,x,t,r_ij,neighbors,pairwise_mask,f_ij,Wf1,bf1,Wf2,bf2,Wq,Wk,Wv,Wo,bo
    const float* x         = (const float*)d_in[1];
    const float* r_ij      = (const float*)d_in[3];
    const int*   neighbors = (const int*)  d_in[4];
    const int*   pmask     = (const int*)  d_in[5];
    const float* f_ij      = (const float*)d_in[6];
    const float* Wf1       = (const float*)d_in[7];
    const float* bf1       = (const float*)d_in[8];
    const float* Wf2       = (const float*)d_in[9];
    const float* bf2       = (const float*)d_in[10];
    const float* Wq        = (const float*)d_in[11];
    const float* Wk        = (const float*)d_in[12];
    const float* Wv        = (const float*)d_in[13];
    const float* Wo        = (const float*)d_in[14];
    const float* bo        = (const float*)d_in[15];

    float* out  = (float*)d_out;
    float* outM = out;                        // m: [B,Na,F]
    float* outW = out + (size_t)NAB * FF;     // W: [B,Na,Nn,F]

    size_t smG = (size_t)(FF*64 + 64*FF) * sizeof(float);   // 64 KB
    size_t smF = SM_TOT;                                    // 104 KB

    cudaFuncSetAttribute(qkv_kernel,    cudaFuncAttributeMaxDynamicSharedMemorySize, (int)smG);
    cudaFuncSetAttribute(filter_kernel, cudaFuncAttributeMaxDynamicSharedMemorySize, (int)smF);

    qkv_kernel<<<dim3(NAB/64, 6), 256, smG>>>(x, Wq, Wk, Wv);
    filter_kernel<<<304, 256, smF>>>(f_ij, r_ij, Wf1, bf1, Wf2, bf2, outW);
    attn_out_kernel<<<NAB, 128>>>(neighbors, pmask, outW, Wo, bo, outM);
}